// round 3
// baseline (speedup 1.0000x reference)
#include <cuda_runtime.h>
#include <cuda_fp16.h>
#include <cuda_bf16.h>
#include <cstdint>

#define IN_FEATS 128
#define HIDDEN   256
#define NMAX     100000

// fp16 per-node projections: u = Hs@W1a + b1, v = Hd@W1b
__device__ unsigned short g_u[(size_t)NMAX * HIDDEN];
__device__ unsigned short g_v[(size_t)NMAX * HIDDEN];

// ---------------------------------------------------------------------------
// helpers
// ---------------------------------------------------------------------------
__device__ __forceinline__ uint32_t smem_u32(const void* p) {
    uint32_t a;
    asm("{ .reg .u64 t; cvta.to.shared.u64 t, %1; cvt.u32.u64 %0, t; }"
        : "=r"(a) : "l"(p));
    return a;
}

// row-local XOR swizzle: rows are 256B (128 bf16). chunk(16B) ^= (row & 7).
__device__ __forceinline__ uint32_t swz(uint32_t row, uint32_t kbyte) {
    return row * 256u + ((((kbyte >> 4) ^ (row & 7u)) << 4) | (kbyte & 15u));
}

__device__ __forceinline__ void ldsm4(uint32_t* r, uint32_t a) {
    asm volatile("ldmatrix.sync.aligned.m8n8.x4.shared.b16 {%0,%1,%2,%3}, [%4];"
                 : "=r"(r[0]), "=r"(r[1]), "=r"(r[2]), "=r"(r[3]) : "r"(a));
}

__device__ __forceinline__ void mma16816(float* d, const uint32_t* a,
                                         const uint32_t* b) {
    asm volatile(
        "mma.sync.aligned.m16n8k16.row.col.f32.bf16.bf16.f32 "
        "{%0,%1,%2,%3}, {%4,%5,%6,%7}, {%8,%9}, {%0,%1,%2,%3};"
        : "+f"(d[0]), "+f"(d[1]), "+f"(d[2]), "+f"(d[3])
        : "r"(a[0]), "r"(a[1]), "r"(a[2]), "r"(a[3]), "r"(b[0]), "r"(b[1]));
}

// SMEM layout (dynamic): Ah | Al | Bh | Bl
static constexpr int SM_AH = 0;          // 128 rows x 256B = 32KB
static constexpr int SM_AL = 32768;
static constexpr int SM_BH = 65536;      // 256 rows x 256B = 64KB
static constexpr int SM_BL = 131072;
static constexpr int SM_TOTAL = 196608;  // 192KB

// ---------------------------------------------------------------------------
// Node GEMM via mma.sync (HMMA): C[128,256] = A[128,128] @ B[128,256]
// bf16 3-term split for fp32-grade accuracy: Ah@Bh + Ah@Bl + Al@Bh.
// 8 warps as 2(M) x 4(N); each warp computes 64x64.
// blockIdx.z: 0 -> u (A=Hs, B=W1[0:128], +b1), 1 -> v (A=Hd, B=W1[128:256])
// ---------------------------------------------------------------------------
__global__ __launch_bounds__(256, 1)
void node_gemm_mma(const float* __restrict__ Hs,
                   const float* __restrict__ Hd,
                   const float* __restrict__ W1,
                   const float* __restrict__ b1,
                   int M)
{
    extern __shared__ char smem[];
    __shared__ float sB1[HIDDEN];
    const uint32_t smb = smem_u32(smem);

    const int tid  = threadIdx.x;
    const int wid  = tid >> 5;
    const int lane = tid & 31;

    const bool is_u = (blockIdx.z == 0);
    const float* __restrict__ A  = is_u ? Hs : Hd;
    const float* __restrict__ Bg = W1 + (is_u ? 0 : (size_t)IN_FEATS * HIDDEN);
    unsigned short* __restrict__ C = is_u ? g_u : g_v;
    const int bm = blockIdx.y * 128;

    if (tid < HIDDEN) sB1[tid] = b1[tid];
    if (tid + 256 < HIDDEN) sB1[tid + 256] = b1[tid + 256];

    // ---- fill A (hi/lo): thread t -> row t/2, k-half (t&1)*64 ----
    {
        const int row   = tid >> 1;
        const int khalf = (tid & 1) * 64;
        const int grow  = bm + row;
        const bool valid = grow < M;
        const float* ar = A + (size_t)grow * IN_FEATS;
        #pragma unroll
        for (int j = 0; j < 16; j++) {
            const int k = khalf + j * 4;
            float4 x = valid ? *reinterpret_cast<const float4*>(ar + k)
                             : make_float4(0.f, 0.f, 0.f, 0.f);
            __nv_bfloat16 h0 = __float2bfloat16(x.x), h1 = __float2bfloat16(x.y);
            __nv_bfloat16 h2 = __float2bfloat16(x.z), h3 = __float2bfloat16(x.w);
            __nv_bfloat16 l0 = __float2bfloat16(x.x - __bfloat162float(h0));
            __nv_bfloat16 l1 = __float2bfloat16(x.y - __bfloat162float(h1));
            __nv_bfloat16 l2 = __float2bfloat16(x.z - __bfloat162float(h2));
            __nv_bfloat16 l3 = __float2bfloat16(x.w - __bfloat162float(h3));
            const uint32_t o = swz((uint32_t)row, (uint32_t)(k * 2));
            __nv_bfloat162 hv0(h0, h1), hv1(h2, h3), lv0(l0, l1), lv1(l2, l3);
            uint2 hv, lv;
            hv.x = *reinterpret_cast<uint32_t*>(&hv0);
            hv.y = *reinterpret_cast<uint32_t*>(&hv1);
            lv.x = *reinterpret_cast<uint32_t*>(&lv0);
            lv.y = *reinterpret_cast<uint32_t*>(&lv1);
            *reinterpret_cast<uint2*>(smem + SM_AH + o) = hv;
            *reinterpret_cast<uint2*>(smem + SM_AL + o) = lv;
        }
    }
    // ---- fill B (hi/lo): Bs[n][k] = Bg[k][n]; coalesced reads over n ----
    #pragma unroll
    for (int i = 0; i < 32; i++) {
        const int linear = tid + i * 256;       // over 128k x 64 float4-groups
        const int k  = linear >> 6;
        const int n0 = (linear & 63) * 4;
        const float4 x = *reinterpret_cast<const float4*>(
            Bg + (size_t)k * HIDDEN + n0);
        const float v[4] = {x.x, x.y, x.z, x.w};
        #pragma unroll
        for (int j = 0; j < 4; j++) {
            __nv_bfloat16 h = __float2bfloat16(v[j]);
            __nv_bfloat16 l = __float2bfloat16(v[j] - __bfloat162float(h));
            const uint32_t o = swz((uint32_t)(n0 + j), (uint32_t)(k * 2));
            *reinterpret_cast<__nv_bfloat16*>(smem + SM_BH + o) = h;
            *reinterpret_cast<__nv_bfloat16*>(smem + SM_BL + o) = l;
        }
    }
    __syncthreads();

    // ---- compute: warp tile 64(M) x 64(N) ----
    const int mbase = (wid >> 2) * 64;
    const int nbase = (wid & 3) * 64;

    float acc[4][8][4];
    #pragma unroll
    for (int mt = 0; mt < 4; mt++)
        #pragma unroll
        for (int nt = 0; nt < 8; nt++)
            #pragma unroll
            for (int q = 0; q < 4; q++) acc[mt][nt][q] = 0.f;

    // ldmatrix lane address components (constant across ksteps)
    const uint32_t rowA  = (uint32_t)(mbase + (lane & 15));
    const uint32_t xorA  = rowA & 7u;
    const uint32_t chA0  = (uint32_t)(lane >> 4);        // 0/1 -> k-chunk half
    const uint32_t baseA = rowA * 256u;

    const uint32_t rowB  = (uint32_t)(nbase + (lane & 7) + ((lane >> 4) << 3));
    const uint32_t xorB  = rowB & 7u;
    const uint32_t chB0  = (uint32_t)((lane >> 3) & 1);
    const uint32_t baseB = rowB * 256u;

    #pragma unroll
    for (int term = 0; term < 3; term++) {
        const uint32_t aBase = smb + (term == 2 ? SM_AL : SM_AH);
        const uint32_t bBase = smb + (term == 1 ? SM_BL : SM_BH);
        #pragma unroll
        for (int ks = 0; ks < 8; ks++) {
            const uint32_t aAddr0 =
                aBase + baseA + (((chA0 + 2u * ks) ^ xorA) << 4);
            const uint32_t bAddr0 =
                bBase + baseB + (((chB0 + 2u * ks) ^ xorB) << 4);
            uint32_t af[4][4], bf[4][4];
            #pragma unroll
            for (int mt = 0; mt < 4; mt++)
                ldsm4(af[mt], aAddr0 + mt * 16 * 256);
            #pragma unroll
            for (int bt = 0; bt < 4; bt++)
                ldsm4(bf[bt], bAddr0 + bt * 16 * 256);
            #pragma unroll
            for (int mt = 0; mt < 4; mt++)
                #pragma unroll
                for (int bt = 0; bt < 4; bt++) {
                    mma16816(acc[mt][2 * bt],     af[mt], &bf[bt][0]);
                    mma16816(acc[mt][2 * bt + 1], af[mt], &bf[bt][2]);
                }
        }
    }

    // ---- epilogue: +bias (u only), fp16 pack, store ----
    #pragma unroll
    for (int mt = 0; mt < 4; mt++) {
        const int m0 = mbase + mt * 16 + (lane >> 2);
        #pragma unroll
        for (int half = 0; half < 2; half++) {
            const int m = m0 + half * 8;
            const int grow = bm + m;
            if (grow >= M) continue;
            unsigned short* orow = C + (size_t)grow * HIDDEN;
            #pragma unroll
            for (int nt = 0; nt < 8; nt++) {
                const int n = nbase + nt * 8 + (lane & 3) * 2;
                float f0 = acc[mt][nt][2 * half];
                float f1 = acc[mt][nt][2 * half + 1];
                if (is_u) { f0 += sB1[n]; f1 += sB1[n + 1]; }
                __half2 h2 = __floats2half2_rn(f0, f1);
                *reinterpret_cast<__half2*>(orow + n) = h2;
            }
        }
    }
}

// ---------------------------------------------------------------------------
// Edge pass (fp16 tables): one warp per edge, lane owns 8 hidden cols.
// ---------------------------------------------------------------------------
__global__ __launch_bounds__(256)
void edge_score_kernel(const int* __restrict__ src,
                       const int* __restrict__ dst,
                       const float* __restrict__ W2,
                       const float* __restrict__ b2,
                       float* __restrict__ out,
                       int E)
{
    __shared__ float sW2[HIDDEN];
    const int tid = threadIdx.x;
    sW2[tid] = W2[tid];
    __syncthreads();

    const int lane = tid & 31;
    const int warp = tid >> 5;

    const float4 wA = *reinterpret_cast<const float4*>(&sW2[lane * 8]);
    const float4 wB = *reinterpret_cast<const float4*>(&sW2[lane * 8 + 4]);
    const float bias = b2[0];

    const int e = blockIdx.x * 8 + warp;
    if (e >= E) return;

    const int s = src[e];
    const int d = dst[e];
    const uint4 ur =
        reinterpret_cast<const uint4*>(g_u + (size_t)s * HIDDEN)[lane];
    const uint4 vr =
        reinterpret_cast<const uint4*>(g_v + (size_t)d * HIDDEN)[lane];

    const __half2* u2 = reinterpret_cast<const __half2*>(&ur);
    const __half2* v2 = reinterpret_cast<const __half2*>(&vr);

    float acc = 0.f;
    const float w[8] = {wA.x, wA.y, wA.z, wA.w, wB.x, wB.y, wB.z, wB.w};
    #pragma unroll
    for (int i = 0; i < 4; i++) {
        float2 uf = __half22float2(u2[i]);
        float2 vf = __half22float2(v2[i]);
        acc = fmaf(fmaxf(uf.x + vf.x, 0.f), w[2 * i], acc);
        acc = fmaf(fmaxf(uf.y + vf.y, 0.f), w[2 * i + 1], acc);
    }
    #pragma unroll
    for (int o = 16; o > 0; o >>= 1)
        acc += __shfl_xor_sync(0xFFFFFFFFu, acc, o);

    if (lane == 0) out[e] = acc + bias;
}

// ---------------------------------------------------------------------------
extern "C" void kernel_launch(void* const* d_in, const int* in_sizes, int n_in,
                              void* d_out, int out_size)
{
    const float* Hs = (const float*)d_in[0];
    const float* Hd = (const float*)d_in[1];
    const int*   src = (const int*)d_in[2];
    const int*   dst = (const int*)d_in[3];
    const float* W1 = (const float*)d_in[4];
    const float* b1 = (const float*)d_in[5];
    const float* W2 = (const float*)d_in[6];
    const float* b2 = (const float*)d_in[7];
    float* out = (float*)d_out;

    const int M = in_sizes[0] / IN_FEATS;
    const int E = in_sizes[2];

    cudaFuncSetAttribute(node_gemm_mma,
                         cudaFuncAttributeMaxDynamicSharedMemorySize, SM_TOTAL);

    dim3 ggrid(1, (M + 127) / 128, 2);
    node_gemm_mma<<<ggrid, 256, SM_TOTAL>>>(Hs, Hd, W1, b1, M);

    edge_score_kernel<<<(E + 7) / 8, 256>>>(src, dst, W2, b2, out, E);
}